// round 10
// baseline (speedup 1.0000x reference)
#include <cuda_runtime.h>
#include <cuda_fp16.h>

typedef unsigned int u32;

#define DIN 128
#define HID 16
#define NMAX 100000
#define CAP 64

// ---------------- device scratch (static; zero-initialized at load) ----------------
__device__ __align__(128) __half g_hp_h[NMAX * HID];   // fp16 h rows, 32 B each
__device__ __align__(128) __half g_ht_h[NMAX * HID];

// per-node attention dot products, one pair per edge type
__device__ float g_a_pt_src[NMAX], g_a_pt_dst[NMAX];
__device__ float g_a_tt_src[NMAX], g_a_tt_dst[NMAX];
__device__ float g_a_tp_src[NMAX], g_a_tp_dst[NMAX];
__device__ float g_a_pp_src[NMAX], g_a_pp_dst[NMAX];

// bucketed edges, transposed: g_bkt2[(type*CAP + pos)*NMAX + dst] = {src, a_src_bits}
// cnt is self-resetting: gather zeroes it after reading (zero-init at load).
__device__ int g_cnt[4 * NMAX];
__device__ int2 g_bkt2[4 * CAP * NMAX];                // 204.8 MB

// normalized + relu'd per-edge-type outputs (f32)
__device__ __align__(16) float g_out_pt[NMAX * HID];
__device__ __align__(16) float g_out_tt[NMAX * HID];
__device__ __align__(16) float g_out_tp[NMAX * HID];
__device__ __align__(16) float g_out_pp[NMAX * HID];

// semantic accumulators (consumers reset them after use; zero-init at load)
__device__ float g_S_p[2 * HID];    // tanh sums (attn scores), reset by attn_kernel
__device__ float g_S_t[2 * HID];
__device__ float g_Z[4 * HID];      // plain sums Σ_n z: [tp, pp, pt, tt], reset by final
__device__ float g_attn[4];

__device__ __forceinline__ float2 h2f(u32 u) {
    return __half22float2(*(__half2*)&u);
}

// 256-bit non-coherent global load (sm_100a+): whole 32B h row in one wavefront
__device__ __forceinline__ void ldg_v8(const __half* p, u32* r) {
    asm volatile("ld.global.nc.v8.b32 {%0,%1,%2,%3,%4,%5,%6,%7}, [%8];"
                 : "=r"(r[0]), "=r"(r[1]), "=r"(r[2]), "=r"(r[3]),
                   "=r"(r[4]), "=r"(r[5]), "=r"(r[6]), "=r"(r[7])
                 : "l"(p));
}

// ---------------- fused projection + attention dots (which = arg) ----------------
// 128 threads, 64 nodes/block, 2 threads per node (8 outputs each, registers).
__global__ __launch_bounds__(128) void proj_dots_kernel(
    const float* __restrict__ x, const float* __restrict__ w,
    const float* __restrict__ b, int which,
    const float* __restrict__ av0, const float* __restrict__ av1,
    const float* __restrict__ av2, const float* __restrict__ av3, int n)
{
    __shared__ float xs[64][DIN + 5];     // row stride 133: conflict-free
    __shared__ float ws[DIN][HID];
    __shared__ float bs[HID];
    __shared__ float sa[4][HID];
    int tid = threadIdx.x;
    for (int idx = tid; idx < DIN * HID; idx += 128)
        ws[idx / HID][idx % HID] = w[idx];
    if (tid < HID) bs[tid] = b[tid];
    if (tid < 4 * HID) {
        const float* src = (tid < 16) ? av0 : (tid < 32) ? av1 : (tid < 48) ? av2 : av3;
        sa[tid / HID][tid % HID] = src[tid % HID];
    }
    int base = blockIdx.x * 64;
    for (int l = tid; l < 64 * DIN; l += 128) {
        int node = l >> 7, j = l & 127;
        xs[node][j] = (base + node < n) ? x[(size_t)(base + node) * DIN + j] : 0.f;
    }
    __syncthreads();

    int ni = tid >> 1;
    int half = tid & 1;
    int ko = half * 8;
    float acc[8];
#pragma unroll
    for (int k = 0; k < 8; k++) acc[k] = bs[ko + k];
#pragma unroll 4
    for (int j = 0; j < DIN; j++) {
        float xv = xs[ni][j];
        float4 w0 = *(float4*)&ws[j][ko];
        float4 w1 = *(float4*)&ws[j][ko + 4];
        acc[0] += xv * w0.x; acc[1] += xv * w0.y;
        acc[2] += xv * w0.z; acc[3] += xv * w0.w;
        acc[4] += xv * w1.x; acc[5] += xv * w1.y;
        acc[6] += xv * w1.z; acc[7] += xv * w1.w;
    }
    int node = base + ni;
    if (node < n) {
        __half* hh = which ? g_ht_h : g_hp_h;
        __half2 p0 = __floats2half2_rn(acc[0], acc[1]);
        __half2 p1 = __floats2half2_rn(acc[2], acc[3]);
        __half2 p2 = __floats2half2_rn(acc[4], acc[5]);
        __half2 p3 = __floats2half2_rn(acc[6], acc[7]);
        uint4 pk;
        pk.x = *(u32*)&p0; pk.y = *(u32*)&p1;
        pk.z = *(u32*)&p2; pk.w = *(u32*)&p3;
        *(uint4*)(hh + (size_t)node * HID + ko) = pk;
    }
    float pd[4];
#pragma unroll
    for (int m = 0; m < 4; m++) {
        float d = 0.f;
#pragma unroll
        for (int k = 0; k < 8; k++) d += acc[k] * sa[m][ko + k];
        pd[m] = d;
    }
#pragma unroll
    for (int m = 0; m < 4; m++)
        pd[m] += __shfl_xor_sync(0xffffffffu, pd[m], 1);
    if (half == 0 && node < n) {
        if (which == 0) {           // from hp
            g_a_pt_src[node] = pd[0];
            g_a_tp_dst[node] = pd[1];
            g_a_pp_src[node] = pd[2];
            g_a_pp_dst[node] = pd[3];
        } else {                    // from ht
            g_a_pt_dst[node] = pd[0];
            g_a_tt_src[node] = pd[1];
            g_a_tt_dst[node] = pd[2];
            g_a_tp_src[node] = pd[3];
        }
    }
}

// ---------------- edge scatter: bucket (src, a_src) by dst, 4 edges/thread ----------------
__global__ __launch_bounds__(256) void edge_scatter(
    const int* __restrict__ e_pt, const int* __restrict__ e_tt,
    const int* __restrict__ e_tp, const int* __restrict__ e_pp,
    int E_pt, int E_tt, int E_tp, int E_pp)
{
    int type = blockIdx.y;
    const int* e; int E;
    const float* asrc;
    switch (type) {
        case 0:  e = e_pt; E = E_pt; asrc = g_a_pt_src; break;
        case 1:  e = e_tt; E = E_tt; asrc = g_a_tt_src; break;
        case 2:  e = e_tp; E = E_tp; asrc = g_a_tp_src; break;
        default: e = e_pp; E = E_pp; asrc = g_a_pp_src; break;
    }
    int* cnt = g_cnt + type * NMAX;
    int2* bkt = g_bkt2 + (size_t)type * CAP * NMAX;
    long t = blockIdx.x * 256L + threadIdx.x;
    int i0 = (int)(t * 4);
    if (i0 >= E) return;
    if (((E & 3) == 0) && (i0 + 3 < E)) {
        int4 s4 = __ldg((const int4*)e + t);
        int4 d4 = __ldg((const int4*)(e + E) + t);
        int ss[4]; ss[0] = s4.x; ss[1] = s4.y; ss[2] = s4.z; ss[3] = s4.w;
        int dd[4]; dd[0] = d4.x; dd[1] = d4.y; dd[2] = d4.z; dd[3] = d4.w;
        float av[4];
#pragma unroll
        for (int k = 0; k < 4; k++) av[k] = __ldg(asrc + ss[k]);
#pragma unroll
        for (int k = 0; k < 4; k++) {
            int pos = atomicAdd(cnt + dd[k], 1);
            if (pos < CAP) {
                int2 v; v.x = ss[k]; v.y = __float_as_int(av[k]);
                bkt[(size_t)pos * NMAX + dd[k]] = v;
            }
        }
    } else {
        int iend = min(i0 + 4, E);
        for (int i = i0; i < iend; i++) {
            int si = __ldg(e + i);
            int di = __ldg(e + E + i);
            float avv = __ldg(asrc + si);
            int pos = atomicAdd(cnt + di, 1);
            if (pos < CAP) {
                int2 v; v.x = si; v.y = __float_as_int(avv);
                bkt[(size_t)pos * NMAX + di] = v;
            }
        }
    }
}

// ---------------- edge gather: per-dst softmax-aggregate; resets cnt ----------------
__global__ __launch_bounds__(256) void edge_gather(int n) {
    int type = blockIdx.y;
    const float* adst;
    const __half* h;
    float* out;
    switch (type) {
        case 0:  adst = g_a_pt_dst; h = g_hp_h; out = g_out_pt; break;
        case 1:  adst = g_a_tt_dst; h = g_ht_h; out = g_out_tt; break;
        case 2:  adst = g_a_tp_dst; h = g_ht_h; out = g_out_tp; break;
        default: adst = g_a_pp_dst; h = g_hp_h; out = g_out_pp; break;
    }
    int d = blockIdx.x * blockDim.x + threadIdx.x;
    if (d >= n) return;
    int c = g_cnt[type * NMAX + d];
    g_cnt[type * NMAX + d] = 0;     // self-reset for next graph replay
    c = min(c, CAP);
    float ad = __ldg(adst + d);
    const int2* b = g_bkt2 + (size_t)(type * CAP) * NMAX + d;   // stride NMAX per pos
    float acc[HID];
#pragma unroll
    for (int k = 0; k < HID; k++) acc[k] = 0.f;
    float sacc = 0.f;
#pragma unroll 2
    for (int j = 0; j < c; j++) {
        int2 v = __ldg(b + (size_t)j * NMAX);
        int si = v.x;
        float a = __int_as_float(v.y) + ad;
        a = (a > 0.f) ? a : 0.2f * a;
        float ef = __expf(a);
        sacc += ef;
        u32 r[8];
        ldg_v8(h + (size_t)si * HID, r);
        float2 f;
        f = h2f(r[0]); acc[0]  += ef * f.x; acc[1]  += ef * f.y;
        f = h2f(r[1]); acc[2]  += ef * f.x; acc[3]  += ef * f.y;
        f = h2f(r[2]); acc[4]  += ef * f.x; acc[5]  += ef * f.y;
        f = h2f(r[3]); acc[6]  += ef * f.x; acc[7]  += ef * f.y;
        f = h2f(r[4]); acc[8]  += ef * f.x; acc[9]  += ef * f.y;
        f = h2f(r[5]); acc[10] += ef * f.x; acc[11] += ef * f.y;
        f = h2f(r[6]); acc[12] += ef * f.x; acc[13] += ef * f.y;
        f = h2f(r[7]); acc[14] += ef * f.x; acc[15] += ef * f.y;
    }
    float inv = 1.f / (sacc + 1e-16f);
    float* ob = out + (size_t)d * HID;
#pragma unroll
    for (int cidx = 0; cidx < 4; cidx++) {
        float4 o;
        o.x = fmaxf(acc[4 * cidx + 0] * inv, 0.f);
        o.y = fmaxf(acc[4 * cidx + 1] * inv, 0.f);
        o.z = fmaxf(acc[4 * cidx + 2] * inv, 0.f);
        o.w = fmaxf(acc[4 * cidx + 3] * inv, 0.f);
        *(float4*)(ob + 4 * cidx) = o;
    }
}

// ---------------- semantic reduce: tanh-sums for attn scores AND plain sums Σ_n z ----------------
// g_Z layout: [0:16)=tp, [16:32)=pp, [32:48)=pt, [48:64)=tt
__global__ __launch_bounds__(256) void sem_reduce_kernel(
    const float* __restrict__ kw, const float* __restrict__ kb, int n)
{
    int which = blockIdx.y;
    __shared__ float ksm[HID * HID];
    __shared__ float kbs[HID];
    __shared__ float acc[4 * HID];    // [v0, v1, z0sum, z1sum]
    int tid = threadIdx.x;
    if (tid < HID * HID) ksm[tid] = kw[tid];
    if (tid < HID) kbs[tid] = kb[tid];
    if (tid < 4 * HID) acc[tid] = 0.f;
    __syncthreads();

    const float *out0, *out1;
    if (which == 0) { out0 = g_out_tp; out1 = g_out_pp; }
    else            { out0 = g_out_pt; out1 = g_out_tt; }

    int i = blockIdx.x * blockDim.x + tid;
    float v0[HID], v1[HID], z0[HID], z1[HID];
    if (i < n) {
        const float4* o0 = (const float4*)(out0 + (size_t)i * HID);
        const float4* o1 = (const float4*)(out1 + (size_t)i * HID);
#pragma unroll
        for (int c = 0; c < 4; c++) {
            float4 a = o0[c], b = o1[c];
            z0[4*c+0] = a.x; z0[4*c+1] = a.y; z0[4*c+2] = a.z; z0[4*c+3] = a.w;
            z1[4*c+0] = b.x; z1[4*c+1] = b.y; z1[4*c+2] = b.z; z1[4*c+3] = b.w;
        }
#pragma unroll
        for (int k = 0; k < HID; k++) {
            float d0 = kbs[k], d1 = kbs[k];
#pragma unroll
            for (int j = 0; j < HID; j++) {
                float kk = ksm[j * HID + k];
                d0 += z0[j] * kk;
                d1 += z1[j] * kk;
            }
            v0[k] = tanhf(d0);
            v1[k] = tanhf(d1);
        }
    } else {
#pragma unroll
        for (int k = 0; k < HID; k++) { v0[k] = 0.f; v1[k] = 0.f; z0[k] = 0.f; z1[k] = 0.f; }
    }
#pragma unroll
    for (int k = 0; k < HID; k++) {
#pragma unroll
        for (int off = 16; off > 0; off >>= 1) {
            v0[k] += __shfl_xor_sync(0xffffffffu, v0[k], off);
            v1[k] += __shfl_xor_sync(0xffffffffu, v1[k], off);
            z0[k] += __shfl_xor_sync(0xffffffffu, z0[k], off);
            z1[k] += __shfl_xor_sync(0xffffffffu, z1[k], off);
        }
    }
    if ((tid & 31) == 0) {
#pragma unroll
        for (int k = 0; k < HID; k++) {
            atomicAdd(&acc[k], v0[k]);
            atomicAdd(&acc[HID + k], v1[k]);
            atomicAdd(&acc[2 * HID + k], z0[k]);
            atomicAdd(&acc[3 * HID + k], z1[k]);
        }
    }
    __syncthreads();
    float* S = (which == 0) ? g_S_p : g_S_t;
    float* Z = g_Z + which * 2 * HID;
    if (tid < 2 * HID) {
        atomicAdd(&S[tid], acc[tid]);
        atomicAdd(&Z[tid], acc[2 * HID + tid]);
    }
}

// ---------------- semantic attention softmax; resets g_S ----------------
__global__ void attn_kernel(const float* __restrict__ q, int n) {
    float invn = 1.f / (float)n;
    float sc[4];
    for (int m = 0; m < 2; m++) {
        float sp = 0.f, st = 0.f;
        for (int k = 0; k < HID; k++) {
            sp += q[k] * g_S_p[m * HID + k];
            st += q[k] * g_S_t[m * HID + k];
        }
        sc[m] = sp * invn;
        sc[2 + m] = st * invn;
    }
    {
        float m = fmaxf(sc[0], sc[1]);
        float e0 = __expf(sc[0] - m), e1 = __expf(sc[1] - m);
        g_attn[0] = e0 / (e0 + e1);
        g_attn[1] = e1 / (e0 + e1);
    }
    {
        float m = fmaxf(sc[2], sc[3]);
        float e0 = __expf(sc[2] - m), e1 = __expf(sc[3] - m);
        g_attn[2] = e0 / (e0 + e1);
        g_attn[3] = e1 / (e0 + e1);
    }
    for (int i = 0; i < 2 * HID; i++) { g_S_p[i] = 0.f; g_S_t[i] = 0.f; }
}

// ---------------- final: out = (Σ_m attn_m Z_m) · lin_w + lin_b; resets g_Z ----------------
// Valid because out_m >= 0 and attn_m > 0 make the outer relu an identity.
__global__ void final_kernel(const float* __restrict__ lw, const float* __restrict__ lb,
                             float* __restrict__ out) {
    float a0 = g_attn[0], a1 = g_attn[1], a2 = g_attn[2], a3 = g_attn[3];
    float r = lb[0];
    for (int k = 0; k < HID; k++) {
        float pooled = a0 * g_Z[k] + a1 * g_Z[HID + k]
                     + a2 * g_Z[2 * HID + k] + a3 * g_Z[3 * HID + k];
        r += pooled * lw[k];
    }
    out[0] = r;
    for (int i = 0; i < 4 * HID; i++) g_Z[i] = 0.f;
}

// ---------------- launch ----------------
extern "C" void kernel_launch(void* const* d_in, const int* in_sizes, int n_in,
                              void* d_out, int out_size)
{
    const float* x_place  = (const float*)d_in[0];
    const float* x_trans  = (const float*)d_in[1];
    const float* w_p      = (const float*)d_in[2];
    const float* b_p      = (const float*)d_in[3];
    const float* w_t      = (const float*)d_in[4];
    const float* b_t      = (const float*)d_in[5];
    const float* a_src_pt = (const float*)d_in[6];
    const float* a_dst_pt = (const float*)d_in[7];
    const float* a_src_tp = (const float*)d_in[8];
    const float* a_dst_tp = (const float*)d_in[9];
    const float* a_src_pp = (const float*)d_in[10];
    const float* a_dst_pp = (const float*)d_in[11];
    const float* a_src_tt = (const float*)d_in[12];
    const float* a_dst_tt = (const float*)d_in[13];
    const float* q        = (const float*)d_in[14];
    const float* k_w      = (const float*)d_in[15];
    const float* k_b      = (const float*)d_in[16];
    const float* lin_w    = (const float*)d_in[17];
    const float* lin_b    = (const float*)d_in[18];
    const int* e_pt = (const int*)d_in[19];
    const int* e_tp = (const int*)d_in[20];
    const int* e_pp = (const int*)d_in[21];
    const int* e_tt = (const int*)d_in[22];

    int N    = in_sizes[0] / DIN;
    int E_pt = in_sizes[19] / 2;
    int E_tp = in_sizes[20] / 2;
    int E_pp = in_sizes[21] / 2;
    int E_tt = in_sizes[22] / 2;

    int pb = (N + 63) / 64;
    proj_dots_kernel<<<pb, 128>>>(x_place, w_p, b_p, 0,
                                  a_src_pt, a_dst_tp, a_src_pp, a_dst_pp, N);  // 0
    proj_dots_kernel<<<pb, 128>>>(x_trans, w_t, b_t, 1,
                                  a_dst_pt, a_src_tt, a_dst_tt, a_src_tp, N);  // 1

    int Emax = max(max(E_pt, E_tt), max(E_tp, E_pp));
    int rows = (Emax + 3) / 4;
    dim3 sg2((rows + 255) / 256, 4);
    edge_scatter<<<sg2, 256>>>(e_pt, e_tt, e_tp, e_pp,
                               E_pt, E_tt, E_tp, E_pp);                        // 2

    int nb = (N + 255) / 256;
    dim3 gg(nb, 4);
    edge_gather<<<gg, 256>>>(N);                                               // 3 (ncu slot)

    dim3 semg(nb, 2);
    sem_reduce_kernel<<<semg, 256>>>(k_w, k_b, N);                             // 4
    attn_kernel<<<1, 1>>>(q, N);                                               // 5
    final_kernel<<<1, 1>>>(lin_w, lin_b, (float*)d_out);                       // 6
}